// round 15
// baseline (speedup 1.0000x reference)
#include <cuda_runtime.h>

// Problem-fixed shapes
#define NCAM  6
#define DDIM  118
#define FH_   32
#define FW_   88
#define CC    80
#define NXV   360
#define NYV   360
#define NZV   1
#define NPOS  (NXV * NYV)                  // 129600 BEV positions
#define NGRP  (NCAM * DDIM * FW_)          // 62304 (n,d,w) groups, 32 h's each
#define HSTRIDE (FW_ * CC)                 // 7040 floats between h rows

// Per-camera precomputed transforms (written by init block 0 BEFORE it
// triggers programmatic launch -> visible to the scatter's prologue)
__device__ float g_M[NCAM * 9];    // extra_rots @ c2l_rots @ inv(intrins)
__device__ float g_T[NCAM * 3];    // extra_rots @ c2l_trans + extra_trans
__device__ float g_iPR[NCAM * 9];  // inv(post_rots)
__device__ float g_pT[NCAM * 3];   // post_trans

__device__ __forceinline__ void inv3(const float* a, float* o) {
    float c00 = a[4] * a[8] - a[5] * a[7];
    float c01 = a[5] * a[6] - a[3] * a[8];
    float c02 = a[3] * a[7] - a[4] * a[6];
    float det = a[0] * c00 + a[1] * c01 + a[2] * c02;
    float id = 1.0f / det;
    o[0] = c00 * id;
    o[1] = (a[2] * a[7] - a[1] * a[8]) * id;
    o[2] = (a[1] * a[5] - a[2] * a[4]) * id;
    o[3] = c01 * id;
    o[4] = (a[0] * a[8] - a[2] * a[6]) * id;
    o[5] = (a[2] * a[3] - a[0] * a[5]) * id;
    o[6] = c02 * id;
    o[7] = (a[1] * a[6] - a[0] * a[7]) * id;
    o[8] = (a[0] * a[4] - a[1] * a[3]) * id;
}

// Streaming (evict-first) float4 load: x is touched exactly once, so keep it
// out of L2's way — preserves residency for `out` (zeroed lines + atomics).
__device__ __forceinline__ float4 ldcs4(const float4* p) {
    float4 v;
    asm volatile("ld.global.cs.v4.f32 {%0, %1, %2, %3}, [%4];"
                 : "=f"(v.x), "=f"(v.y), "=f"(v.z), "=f"(v.w)
                 : "l"(p));
    return v;
}

// Init: zero out + camera matrices (block 0). Single wave; block 0 triggers
// PDL only after matrices are written+fenced.
#define ZBLOCKS 592
__global__ __launch_bounds__(256) void init_kernel(float4* __restrict__ out4,
                                                   int n4,
                                                   const float* __restrict__ c2l_r,
                                                   const float* __restrict__ c2l_t,
                                                   const float* __restrict__ intr,
                                                   const float* __restrict__ post_r,
                                                   const float* __restrict__ post_t,
                                                   const float* __restrict__ extra_r,
                                                   const float* __restrict__ extra_t) {
    if (blockIdx.x == 0) {
        if (threadIdx.x < NCAM) {
            int n = threadIdx.x;
            float iK[9];
            inv3(intr + n * 9, iK);

            const float* R = c2l_r + n * 9;
            float comb[9];
#pragma unroll
            for (int i = 0; i < 3; i++)
#pragma unroll
                for (int j = 0; j < 3; j++)
                    comb[i * 3 + j] = R[i * 3 + 0] * iK[0 * 3 + j] +
                                      R[i * 3 + 1] * iK[1 * 3 + j] +
                                      R[i * 3 + 2] * iK[2 * 3 + j];

            const float* E = extra_r;
#pragma unroll
            for (int i = 0; i < 3; i++)
#pragma unroll
                for (int j = 0; j < 3; j++)
                    g_M[n * 9 + i * 3 + j] = E[i * 3 + 0] * comb[0 * 3 + j] +
                                             E[i * 3 + 1] * comb[1 * 3 + j] +
                                             E[i * 3 + 2] * comb[2 * 3 + j];

            const float* t = c2l_t + n * 3;
#pragma unroll
            for (int i = 0; i < 3; i++)
                g_T[n * 3 + i] = E[i * 3 + 0] * t[0] + E[i * 3 + 1] * t[1] +
                                 E[i * 3 + 2] * t[2] + extra_t[i];

            float iPR[9];
            inv3(post_r + n * 9, iPR);
#pragma unroll
            for (int i = 0; i < 9; i++) g_iPR[n * 9 + i] = iPR[i];
#pragma unroll
            for (int i = 0; i < 3; i++) g_pT[n * 3 + i] = post_t[n * 3 + i];
            __threadfence();
        }
        __syncthreads();
        cudaTriggerProgrammaticLaunchCompletion();
    } else {
        cudaTriggerProgrammaticLaunchCompletion();
    }

    const float4 z = make_float4(0.f, 0.f, 0.f, 0.f);
    int stride = ZBLOCKS * 256;
    for (int idx = (int)(blockIdx.x * 256u + threadIdx.x); idx < n4; idx += stride)
        out4[idx] = z;
}

// One warp per (n, d, w) group; lane l owns image row h = l. 512-thread
// blocks (16 warps, 2 blocks/SM -> same 32 warps/SM, fewer blocks to
// dispatch). x loads use evict-first streaming; atomics gated on PDL sync.
#define SBLOCK 512
__global__ __launch_bounds__(SBLOCK, 2) void scatter_kernel(const float* __restrict__ x,
                                                            float* __restrict__ out) {
    int grp = (int)((blockIdx.x * (unsigned)SBLOCK + threadIdx.x) >> 5);
    int lane = threadIdx.x & 31;
    if (grp >= NGRP) {
        cudaGridDependencySynchronize();
        return;
    }

    int w = grp % FW_;
    int nd = grp / FW_;      // n*DDIM + d
    int d = nd % DDIM;
    int n = nd / DDIM;

    float u = (float)w * (703.0f / 87.0f);
    float v = (float)lane * (255.0f / 31.0f);
    float dep = 1.0f + 0.5f * (float)d;

    const float* iPR = g_iPR + n * 9;
    const float* pT = g_pT + n * 3;
    const float* M = g_M + n * 9;
    const float* T = g_T + n * 3;

    float ax = u - pT[0], ay = v - pT[1], az = dep - pT[2];
    float px = iPR[0] * ax + iPR[1] * ay + iPR[2] * az;
    float py = iPR[3] * ax + iPR[4] * ay + iPR[5] * az;
    float pz = iPR[6] * ax + iPR[7] * ay + iPR[8] * az;

    float rx = px * pz, ry = py * pz, rz = pz;

    float gx = M[0] * rx + M[1] * ry + M[2] * rz + T[0];
    float gy = M[3] * rx + M[4] * ry + M[5] * rz + T[1];
    float gz = M[6] * rx + M[7] * ry + M[8] * rz + T[2];

    // voxelize: int32 cast truncates toward zero (matches jnp astype(int32))
    int cx = (int)((gx + 54.0f) * (1.0f / 0.3f));
    int cy = (int)((gy + 54.0f) * (1.0f / 0.3f));
    int cz = (int)((gz + 10.0f) * (1.0f / 20.0f));

    bool valid = (cx >= 0) & (cx < NXV) & (cy >= 0) & (cy < NYV) &
                 (cz >= 0) & (cz < NZV);
    int voxel = valid ? (cx * NYV + cy) : -1;

    unsigned vball = __ballot_sync(0xffffffffu, valid);
    if (vball == 0u) {
        cudaGridDependencySynchronize();
        return;
    }

    const float* base = x + (size_t)nd * (FH_ * HSTRIDE) + (size_t)w * CC;
    bool active = lane < (CC / 4);  // lanes 0..19 carry 4 channels each

    int vref = __shfl_sync(0xffffffffu, voxel, __ffs(vball) - 1);
    bool uni = __all_sync(0xffffffffu, !valid || (voxel == vref));

    if (uni) {
        // ---- fast path: single destination cell, batched streaming loads ----
        float4 acc = make_float4(0.f, 0.f, 0.f, 0.f);
#pragma unroll
        for (int h0 = 0; h0 < FH_; h0 += 8) {
            float4 f[8];
#pragma unroll
            for (int j = 0; j < 8; j++) {
                bool use = active && ((vball >> (h0 + j)) & 1u);
                f[j] = use ? ldcs4((const float4*)(base + (size_t)(h0 + j) * HSTRIDE) + lane)
                           : make_float4(0.f, 0.f, 0.f, 0.f);
            }
#pragma unroll
            for (int j = 0; j < 8; j++) {
                acc.x += f[j].x; acc.y += f[j].y; acc.z += f[j].z; acc.w += f[j].w;
            }
        }
        // out must be fully zeroed before the first atomic lands
        cudaGridDependencySynchronize();
        if (active) {
#pragma unroll
            for (int i = 0; i < 4; i++)
                atomicAdd(out + (size_t)(lane * 4 + i) * NPOS + vref,
                          ((const float*)&acc)[i]);
        }
        return;
    }

    // ---- generic fallback: run-tracking over h ----
    cudaGridDependencySynchronize();
    float4 acc = make_float4(0.f, 0.f, 0.f, 0.f);
    int cur = -1;
#pragma unroll
    for (int hh = 0; hh < FH_; hh++) {
        int vx = __shfl_sync(0xffffffffu, voxel, hh);
        if (vx < 0) continue;
        if (vx != cur) {
            if (cur >= 0 && active) {
#pragma unroll
                for (int i = 0; i < 4; i++)
                    atomicAdd(out + (size_t)(lane * 4 + i) * NPOS + cur,
                              ((const float*)&acc)[i]);
            }
            cur = vx;
            acc = make_float4(0.f, 0.f, 0.f, 0.f);
        }
        if (active) {
            float4 f = ldcs4((const float4*)(base + (size_t)hh * HSTRIDE) + lane);
            acc.x += f.x; acc.y += f.y; acc.z += f.z; acc.w += f.w;
        }
    }
    if (cur >= 0 && active) {
#pragma unroll
        for (int i = 0; i < 4; i++)
            atomicAdd(out + (size_t)(lane * 4 + i) * NPOS + cur,
                      ((const float*)&acc)[i]);
    }
}

extern "C" void kernel_launch(void* const* d_in, const int* in_sizes, int n_in,
                              void* d_out, int out_size) {
    const float* x       = (const float*)d_in[0];
    const float* c2l_r   = (const float*)d_in[1];
    const float* c2l_t   = (const float*)d_in[2];
    const float* intr    = (const float*)d_in[3];
    const float* post_r  = (const float*)d_in[4];
    const float* post_t  = (const float*)d_in[5];
    const float* extra_r = (const float*)d_in[6];
    const float* extra_t = (const float*)d_in[7];
    float* out = (float*)d_out;

    int n4 = out_size / 4;  // 2,592,000 float4
    init_kernel<<<ZBLOCKS, 256>>>((float4*)out, n4, c2l_r, c2l_t, intr,
                                  post_r, post_t, extra_r, extra_t);

    // PDL: scatter's prologue overlaps init; atomics wait on grid-dep sync.
    cudaLaunchConfig_t cfg = {};
    cfg.gridDim = dim3(NGRP / (SBLOCK / 32), 1, 1);   // 3894 blocks
    cfg.blockDim = dim3(SBLOCK, 1, 1);
    cudaLaunchAttribute attr[1];
    attr[0].id = cudaLaunchAttributeProgrammaticStreamSerialization;
    attr[0].val.programmaticStreamSerializationAllowed = 1;
    cfg.attrs = attr;
    cfg.numAttrs = 1;
    cudaLaunchKernelEx(&cfg, scatter_kernel, x, out);
}

// round 16
// speedup vs baseline: 1.0647x; 1.0647x over previous
#include <cuda_runtime.h>

// Problem-fixed shapes
#define NCAM  6
#define DDIM  118
#define FH_   32
#define FW_   88
#define CC    80
#define NXV   360
#define NYV   360
#define NZV   1
#define NPOS  (NXV * NYV)                  // 129600 BEV positions
#define NGRP  (NCAM * DDIM * FW_)          // 62304 (n,d,w) groups, 32 h's each
#define HSTRIDE (FW_ * CC)                 // 7040 floats between h rows

// Per-camera precomputed transforms (written by init block 0 BEFORE it
// triggers programmatic launch -> visible to the scatter's prologue)
__device__ float g_M[NCAM * 9];    // extra_rots @ c2l_rots @ inv(intrins)
__device__ float g_T[NCAM * 3];    // extra_rots @ c2l_trans + extra_trans
__device__ float g_iPR[NCAM * 9];  // inv(post_rots)
__device__ float g_pT[NCAM * 3];   // post_trans

__device__ __forceinline__ void inv3(const float* a, float* o) {
    float c00 = a[4] * a[8] - a[5] * a[7];
    float c01 = a[5] * a[6] - a[3] * a[8];
    float c02 = a[3] * a[7] - a[4] * a[6];
    float det = a[0] * c00 + a[1] * c01 + a[2] * c02;
    float id = 1.0f / det;
    o[0] = c00 * id;
    o[1] = (a[2] * a[7] - a[1] * a[8]) * id;
    o[2] = (a[1] * a[5] - a[2] * a[4]) * id;
    o[3] = c01 * id;
    o[4] = (a[0] * a[8] - a[2] * a[6]) * id;
    o[5] = (a[2] * a[3] - a[0] * a[5]) * id;
    o[6] = c02 * id;
    o[7] = (a[1] * a[6] - a[0] * a[7]) * id;
    o[8] = (a[0] * a[4] - a[1] * a[3]) * id;
}

// Streaming (evict-first) float4 load: x is touched exactly once, so keep it
// out of L2's way — preserves residency for `out` (zeroed lines + atomics).
__device__ __forceinline__ float4 ldcs4(const float4* p) {
    float4 v;
    asm volatile("ld.global.cs.v4.f32 {%0, %1, %2, %3}, [%4];"
                 : "=f"(v.x), "=f"(v.y), "=f"(v.z), "=f"(v.w)
                 : "l"(p));
    return v;
}

// Init: zero out + camera matrices (block 0). Single wave; block 0 triggers
// PDL only after matrices are written+fenced.
#define ZBLOCKS 592
__global__ __launch_bounds__(256) void init_kernel(float4* __restrict__ out4,
                                                   int n4,
                                                   const float* __restrict__ c2l_r,
                                                   const float* __restrict__ c2l_t,
                                                   const float* __restrict__ intr,
                                                   const float* __restrict__ post_r,
                                                   const float* __restrict__ post_t,
                                                   const float* __restrict__ extra_r,
                                                   const float* __restrict__ extra_t) {
    if (blockIdx.x == 0) {
        if (threadIdx.x < NCAM) {
            int n = threadIdx.x;
            float iK[9];
            inv3(intr + n * 9, iK);

            const float* R = c2l_r + n * 9;
            float comb[9];
#pragma unroll
            for (int i = 0; i < 3; i++)
#pragma unroll
                for (int j = 0; j < 3; j++)
                    comb[i * 3 + j] = R[i * 3 + 0] * iK[0 * 3 + j] +
                                      R[i * 3 + 1] * iK[1 * 3 + j] +
                                      R[i * 3 + 2] * iK[2 * 3 + j];

            const float* E = extra_r;
#pragma unroll
            for (int i = 0; i < 3; i++)
#pragma unroll
                for (int j = 0; j < 3; j++)
                    g_M[n * 9 + i * 3 + j] = E[i * 3 + 0] * comb[0 * 3 + j] +
                                             E[i * 3 + 1] * comb[1 * 3 + j] +
                                             E[i * 3 + 2] * comb[2 * 3 + j];

            const float* t = c2l_t + n * 3;
#pragma unroll
            for (int i = 0; i < 3; i++)
                g_T[n * 3 + i] = E[i * 3 + 0] * t[0] + E[i * 3 + 1] * t[1] +
                                 E[i * 3 + 2] * t[2] + extra_t[i];

            float iPR[9];
            inv3(post_r + n * 9, iPR);
#pragma unroll
            for (int i = 0; i < 9; i++) g_iPR[n * 9 + i] = iPR[i];
#pragma unroll
            for (int i = 0; i < 3; i++) g_pT[n * 3 + i] = post_t[n * 3 + i];
            __threadfence();
        }
        __syncthreads();
        cudaTriggerProgrammaticLaunchCompletion();
    } else {
        cudaTriggerProgrammaticLaunchCompletion();
    }

    const float4 z = make_float4(0.f, 0.f, 0.f, 0.f);
    int stride = ZBLOCKS * 256;
    for (int idx = (int)(blockIdx.x * 256u + threadIdx.x); idx < n4; idx += stride)
        out4[idx] = z;
}

// One warp per (n, d, w) group; lane l owns image row h = l. x loads use
// evict-first streaming policy; atomics gated on PDL grid-dependency sync.
__global__ __launch_bounds__(256, 4) void scatter_kernel(const float* __restrict__ x,
                                                         float* __restrict__ out) {
    int grp = (int)((blockIdx.x * (unsigned)blockDim.x + threadIdx.x) >> 5);
    int lane = threadIdx.x & 31;
    if (grp >= NGRP) {
        cudaGridDependencySynchronize();
        return;
    }

    int w = grp % FW_;
    int nd = grp / FW_;      // n*DDIM + d
    int d = nd % DDIM;
    int n = nd / DDIM;

    float u = (float)w * (703.0f / 87.0f);
    float v = (float)lane * (255.0f / 31.0f);
    float dep = 1.0f + 0.5f * (float)d;

    const float* iPR = g_iPR + n * 9;
    const float* pT = g_pT + n * 3;
    const float* M = g_M + n * 9;
    const float* T = g_T + n * 3;

    float ax = u - pT[0], ay = v - pT[1], az = dep - pT[2];
    float px = iPR[0] * ax + iPR[1] * ay + iPR[2] * az;
    float py = iPR[3] * ax + iPR[4] * ay + iPR[5] * az;
    float pz = iPR[6] * ax + iPR[7] * ay + iPR[8] * az;

    float rx = px * pz, ry = py * pz, rz = pz;

    float gx = M[0] * rx + M[1] * ry + M[2] * rz + T[0];
    float gy = M[3] * rx + M[4] * ry + M[5] * rz + T[1];
    float gz = M[6] * rx + M[7] * ry + M[8] * rz + T[2];

    // voxelize: int32 cast truncates toward zero (matches jnp astype(int32))
    int cx = (int)((gx + 54.0f) * (1.0f / 0.3f));
    int cy = (int)((gy + 54.0f) * (1.0f / 0.3f));
    int cz = (int)((gz + 10.0f) * (1.0f / 20.0f));

    bool valid = (cx >= 0) & (cx < NXV) & (cy >= 0) & (cy < NYV) &
                 (cz >= 0) & (cz < NZV);
    int voxel = valid ? (cx * NYV + cy) : -1;

    unsigned vball = __ballot_sync(0xffffffffu, valid);
    if (vball == 0u) {
        cudaGridDependencySynchronize();
        return;
    }

    const float* base = x + (size_t)nd * (FH_ * HSTRIDE) + (size_t)w * CC;
    bool active = lane < (CC / 4);  // lanes 0..19 carry 4 channels each

    int vref = __shfl_sync(0xffffffffu, voxel, __ffs(vball) - 1);
    bool uni = __all_sync(0xffffffffu, !valid || (voxel == vref));

    if (uni) {
        // ---- fast path: single destination cell, batched streaming loads ----
        float4 acc = make_float4(0.f, 0.f, 0.f, 0.f);
#pragma unroll
        for (int h0 = 0; h0 < FH_; h0 += 8) {
            float4 f[8];
#pragma unroll
            for (int j = 0; j < 8; j++) {
                bool use = active && ((vball >> (h0 + j)) & 1u);
                f[j] = use ? ldcs4((const float4*)(base + (size_t)(h0 + j) * HSTRIDE) + lane)
                           : make_float4(0.f, 0.f, 0.f, 0.f);
            }
#pragma unroll
            for (int j = 0; j < 8; j++) {
                acc.x += f[j].x; acc.y += f[j].y; acc.z += f[j].z; acc.w += f[j].w;
            }
        }
        // out must be fully zeroed before the first atomic lands
        cudaGridDependencySynchronize();
        if (active) {
#pragma unroll
            for (int i = 0; i < 4; i++)
                atomicAdd(out + (size_t)(lane * 4 + i) * NPOS + vref,
                          ((const float*)&acc)[i]);
        }
        return;
    }

    // ---- generic fallback: run-tracking over h ----
    cudaGridDependencySynchronize();
    float4 acc = make_float4(0.f, 0.f, 0.f, 0.f);
    int cur = -1;
#pragma unroll
    for (int hh = 0; hh < FH_; hh++) {
        int vx = __shfl_sync(0xffffffffu, voxel, hh);
        if (vx < 0) continue;
        if (vx != cur) {
            if (cur >= 0 && active) {
#pragma unroll
                for (int i = 0; i < 4; i++)
                    atomicAdd(out + (size_t)(lane * 4 + i) * NPOS + cur,
                              ((const float*)&acc)[i]);
            }
            cur = vx;
            acc = make_float4(0.f, 0.f, 0.f, 0.f);
        }
        if (active) {
            float4 f = ldcs4((const float4*)(base + (size_t)hh * HSTRIDE) + lane);
            acc.x += f.x; acc.y += f.y; acc.z += f.z; acc.w += f.w;
        }
    }
    if (cur >= 0 && active) {
#pragma unroll
        for (int i = 0; i < 4; i++)
            atomicAdd(out + (size_t)(lane * 4 + i) * NPOS + cur,
                      ((const float*)&acc)[i]);
    }
}

extern "C" void kernel_launch(void* const* d_in, const int* in_sizes, int n_in,
                              void* d_out, int out_size) {
    const float* x       = (const float*)d_in[0];
    const float* c2l_r   = (const float*)d_in[1];
    const float* c2l_t   = (const float*)d_in[2];
    const float* intr    = (const float*)d_in[3];
    const float* post_r  = (const float*)d_in[4];
    const float* post_t  = (const float*)d_in[5];
    const float* extra_r = (const float*)d_in[6];
    const float* extra_t = (const float*)d_in[7];
    float* out = (float*)d_out;

    int n4 = out_size / 4;  // 2,592,000 float4
    init_kernel<<<ZBLOCKS, 256>>>((float4*)out, n4, c2l_r, c2l_t, intr,
                                  post_r, post_t, extra_r, extra_t);

    // PDL: scatter's prologue overlaps init; atomics wait on grid-dep sync.
    cudaLaunchConfig_t cfg = {};
    cfg.gridDim = dim3(NGRP / 8, 1, 1);   // 7788 blocks
    cfg.blockDim = dim3(256, 1, 1);
    cudaLaunchAttribute attr[1];
    attr[0].id = cudaLaunchAttributeProgrammaticStreamSerialization;
    attr[0].val.programmaticStreamSerializationAllowed = 1;
    cfg.attrs = attr;
    cfg.numAttrs = 1;
    cudaLaunchKernelEx(&cfg, scatter_kernel, x, out);
}